// round 9
// baseline (speedup 1.0000x reference)
#include <cuda_runtime.h>
#include <cstdint>

#define DDIM   128
#define MROWS  131072
#define KHALF  (MROWS/2)

// ---------------- device scratch ----------------
__device__ int      g_rowmap_l[MROWS];
__device__ int      g_rowmap_r[MROWS];
// pass-major pre-swizzled tf32 B fragments:
//  pass0 {i,u}:    words [0,      65536)  16 chunks (K=16, 2 gate slots of 2048 words)
//  pass1 {fl,fr}:  words [65536, 131072)  16 chunks (K=16, 2 gate slots)
//  pass2 {o}:      words [131072,163840)   8 chunks (K=32, 1 slot of 4096 words)
__device__ uint32_t g_Bpack[163840];

// ---------------- helpers ----------------
__device__ __forceinline__ uint32_t smem_u32(const void* p) {
    uint32_t a;
    asm("{ .reg .u64 t; cvta.to.shared.u64 t, %1; cvt.u32.u64 %0, t; }" : "=r"(a) : "l"(p));
    return a;
}
__device__ __forceinline__ uint32_t f2tf32(float f) {
    uint32_t r; asm("cvt.rna.tf32.f32 %0, %1;" : "=r"(r) : "f"(f)); return r;
}
__device__ __forceinline__ float ex2f(float x) {
    float y; asm("ex2.approx.f32 %0, %1;" : "=f"(y) : "f"(x)); return y;
}
__device__ __forceinline__ float rcpf(float x) {
    float y; asm("rcp.approx.f32 %0, %1;" : "=f"(y) : "f"(x)); return y;
}
__device__ __forceinline__ float sigf(float x) {
    return rcpf(1.0f + ex2f(-1.4426950408889634f * x));
}
__device__ __forceinline__ float tanhf_(float x) {
    return fmaf(2.0f, rcpf(1.0f + ex2f(-2.8853900817779268f * x)), -1.0f);
}
__device__ __forceinline__ void mma_tf32(float* d, const uint32_t* a, const uint32_t* b) {
    asm volatile(
        "mma.sync.aligned.m16n8k8.row.col.f32.tf32.tf32.f32 "
        "{%0,%1,%2,%3}, {%4,%5,%6,%7}, {%8,%9}, {%0,%1,%2,%3};"
        : "+f"(d[0]), "+f"(d[1]), "+f"(d[2]), "+f"(d[3])
        : "r"(a[0]), "r"(a[1]), "r"(a[2]), "r"(a[3]), "r"(b[0]), "r"(b[1]));
}
__device__ __forceinline__ void cpa16(uint32_t dst, const uint32_t* src) {
    asm volatile("cp.async.cg.shared.global [%0], [%1], 16;" :: "r"(dst), "l"(src));
}
__device__ __forceinline__ void cp_commit() {
    asm volatile("cp.async.commit_group;" ::: "memory");
}
__device__ __forceinline__ void pf_l2(const void* p) {
    asm volatile("prefetch.global.L2 [%0];" :: "l"(p));
}

// ---------------- SMEM layout (69.6 KB -> 3 CTAs/SM) ----------------
#define SMEM_BIAS  0          // 640 floats = 2560 B
#define SMEM_MAPL  2560       // 32 ints
#define SMEM_MAPR  2688       // 32 ints
#define SMEM_A     4096       // 32x256 tf32 fragment-packed = 32768 B
#define SMEM_B0    36864      // 16 KB
#define SMEM_B1    53248      // 16 KB
#define SMEM_TOTAL 69632

// A pack byte offset (relative to SMEM_A) for element (r,k), r in [0,32)
__device__ __forceinline__ uint32_t a_off(int r, int k) {
    int mt = r >> 4, kk = k >> 3;   // mt in {0,1}
    int lane = ((r & 7) << 2) | (k & 3);
    int slot = ((r >> 3) & 1) | (((k >> 2) & 1) << 1);
    return (uint32_t)((((mt << 5) + kk) << 5) + (lane ^ (kk & 7))) * 16u + (uint32_t)slot * 4u;
}

// ---------------- single merged prep kernel ----------------
__global__ void prep_all(const float* __restrict__ W,
                         const int* __restrict__ bf0, const int* __restrict__ bt0,
                         const int* __restrict__ pf0, const int* __restrict__ pt0,
                         const int* __restrict__ bf1, const int* __restrict__ bt1,
                         const int* __restrict__ pf1, const int* __restrict__ pt1) {
    int idx = blockIdx.x * blockDim.x + threadIdx.x;
    if (idx < KHALF) {
        g_rowmap_l[bt0[idx]] = bf0[idx];
        g_rowmap_l[pt0[idx]] = (int)((uint32_t)pf0[idx] | 0x80000000u);
        g_rowmap_r[bt1[idx]] = bf1[idx];
        g_rowmap_r[pt1[idx]] = (int)((uint32_t)pf1[idx] | 0x80000000u);
    }
    if (idx < 256 * 640) {
        int k = idx / 640, col = idx % 640;
        int gate = col >> 7, n = col & 127;     // gates: 0:i 1:o 2:u 3:f_l 4:f_r
        int pass, slot;
        if      (gate == 0) { pass = 0; slot = 0; }
        else if (gate == 2) { pass = 0; slot = 1; }
        else if (gate == 3) { pass = 1; slot = 0; }
        else if (gate == 4) { pass = 1; slot = 1; }
        else                { pass = 2; slot = 0; }
        int nt = n >> 3, nl = n & 7;
        int kl = k & 7;
        int lane = (nl << 2) | (kl & 3);
        int ws = (kl >> 2) & 1;
        int off;
        if (pass < 2) {  // K-chunk 16, 2 slots of 2048 words
            int chunk = k >> 4, kk = (k >> 3) & 1;
            off = pass * 65536 + chunk * 4096 + slot * 2048
                + ((kk * 8 + (nt >> 1)) * 32 + lane) * 4 + (nt & 1) * 2 + ws;
        } else {         // K-chunk 32, 1 slot of 4096 words
            int chunk = k >> 5, kk = (k >> 3) & 3;
            off = 131072 + chunk * 4096
                + ((kk * 8 + (nt >> 1)) * 32 + lane) * 4 + (nt & 1) * 2 + ws;
        }
        g_Bpack[off] = f2tf32(W[idx]);
    }
}

// ---------------- pipelined MMA pass ----------------
// one 16 KB chunk = 4096 words = 1024 x 16B units
__device__ __forceinline__ void issue_chunk16(uint32_t sdst, const uint32_t* src, int tid) {
    #pragma unroll
    for (int i = 0; i < 4; i++) {
        int unit = i * 256 + tid;
        cpa16(sdst + (uint32_t)unit * 16u, src + unit * 4);
    }
    cp_commit();
}

// Single-sync double-buffered pass. Invariant: chunk0 already in flight to B0.
template<int NS, int NCH, int KS>
__device__ __forceinline__ void run_pass(const uint32_t* __restrict__ gW,
                                         const uint32_t* __restrict__ nextW,
                                         char* smem, uint32_t sbase,
                                         int tid, int wm, int wq, int lane,
                                         float acc[][4][4]) {
    #pragma unroll
    for (int s = 0; s < NS; s++)
        #pragma unroll
        for (int ni = 0; ni < 4; ni++)
            #pragma unroll
            for (int c = 0; c < 4; c++) acc[s][ni][c] = 0.0f;

    #pragma unroll 1
    for (int c = 0; c < NCH; c++) {
        asm volatile("cp.async.wait_group 0;" ::: "memory");   // chunk c landed
        __syncthreads();                                        // visible; prev compute done
        if (c < NCH - 1)
            issue_chunk16(sbase + ((c & 1) ? SMEM_B0 : SMEM_B1), gW + (c + 1) * 4096, tid);
        else if (nextW)
            issue_chunk16(sbase + ((c & 1) ? SMEM_B0 : SMEM_B1), nextW, tid);
        const char* bb = smem + ((c & 1) ? SMEM_B1 : SMEM_B0);

        #pragma unroll
        for (int kk = 0; kk < KS; kk++) {
            const int kkg = c * KS + kk;
            uint32_t a[4];
            {
                uint4 v = *(const uint4*)(smem + SMEM_A +
                    (uint32_t)(((wm * 32 + kkg) * 32) + (lane ^ (kkg & 7))) * 16u);
                a[0] = v.x; a[1] = v.y; a[2] = v.z; a[3] = v.w;
            }
            uint32_t b[NS][4][2];
            #pragma unroll
            for (int s = 0; s < NS; s++)
                #pragma unroll
                for (int np2 = 0; np2 < 2; np2++) {
                    uint4 v = *(const uint4*)(bb + s * 8192 +
                        (uint32_t)(((kk * 8 + wq * 2 + np2) * 32) + lane) * 16u);
                    b[s][np2 * 2][0]     = v.x; b[s][np2 * 2][1]     = v.y;
                    b[s][np2 * 2 + 1][0] = v.z; b[s][np2 * 2 + 1][1] = v.w;
                }
            #pragma unroll
            for (int s = 0; s < NS; s++)
                #pragma unroll
                for (int ni = 0; ni < 4; ni++)
                    mma_tf32(acc[s][ni], a, b[s][ni]);
        }
    }
}

// ---------------- main fused kernel ----------------
__global__ void __launch_bounds__(256, 3) treelstm_main(
    const float* __restrict__ h_bot, const float* __restrict__ c_bot,
    const float* __restrict__ h_buf, const float* __restrict__ c_buf,
    const float* __restrict__ bias,  float* __restrict__ out) {
    extern __shared__ char smem[];
    const uint32_t sbase = smem_u32(smem);
    float* bias_s = (float*)(smem + SMEM_BIAS);
    int*   mapl_s = (int*)(smem + SMEM_MAPL);
    int*   mapr_s = (int*)(smem + SMEM_MAPR);

    const int tid = threadIdx.x, wid = tid >> 5, lane = tid & 31;
    const int g = lane >> 2, tig = lane & 3;
    const int wm = wid & 1, wq = wid >> 1;
    const int blk = blockIdx.x;

    // preload pass0 chunk0 so its latency hides under the A gather
    issue_chunk16(sbase + SMEM_B0, g_Bpack, tid);

    for (int t = tid; t < 640; t += 256) bias_s[t] = bias[t];
    if (tid < 32) {
        mapl_s[tid] = g_rowmap_l[blk * 32 + tid];
        mapr_s[tid] = g_rowmap_r[blk * 32 + tid];
    }

    // ---- gather X = [h_l | h_r] into fragment-packed A (tf32) ----
    // 32 rows x 2 sources = 64 warp-jobs
    for (int j = wid; j < 64; j += 8) {
        int src = j & 1, r = j >> 1;
        int m = blk * 32 + r;
        int map = src ? g_rowmap_r[m] : g_rowmap_l[m];
        const float* sp = ((map < 0) ? h_buf : h_bot) + (size_t)(uint32_t)(map & 0x7fffffff) * DDIM;
        float4 v = ((const float4*)sp)[lane];
        int k0 = src * 128 + lane * 4;
        char* ab = smem + SMEM_A;
        *(uint32_t*)(ab + a_off(r, k0 + 0)) = f2tf32(v.x);
        *(uint32_t*)(ab + a_off(r, k0 + 1)) = f2tf32(v.y);
        *(uint32_t*)(ab + a_off(r, k0 + 2)) = f2tf32(v.z);
        *(uint32_t*)(ab + a_off(r, k0 + 3)) = f2tf32(v.w);
    }

    float acc[2][4][4];
    float creg[4][4];
    const int row0 = wm * 16 + g;          // this thread covers rows row0, row0+8

    // ---- pass 0: gates i & u ----
    run_pass<2, 16, 2>(g_Bpack, g_Bpack + 65536, smem, sbase, tid, wm, wq, lane, acc);
    #pragma unroll
    for (int ni = 0; ni < 4; ni++) {
        int colg = wq * 32 + ni * 8 + tig * 2;
        float2 bi = *(const float2*)(bias_s + colg);         // i: cols 0..127
        float2 bu = *(const float2*)(bias_s + 256 + colg);   // u: cols 256..383
        creg[ni][0] = sigf(acc[0][ni][0] + bi.x) * tanhf_(acc[1][ni][0] + bu.x);
        creg[ni][1] = sigf(acc[0][ni][1] + bi.y) * tanhf_(acc[1][ni][1] + bu.y);
        creg[ni][2] = sigf(acc[0][ni][2] + bi.x) * tanhf_(acc[1][ni][2] + bu.x);
        creg[ni][3] = sigf(acc[0][ni][3] + bi.y) * tanhf_(acc[1][ni][3] + bu.y);
    }

    // ---- L2-prefetch the c_l/c_r rows this thread will gather after pass 1 ----
    {
        const int colb = wq * 32;
        int ml0 = mapl_s[row0], ml1 = mapl_s[row0 + 8];
        int mr0 = mapr_s[row0], mr1 = mapr_s[row0 + 8];
        pf_l2(((ml0 < 0) ? c_buf : c_bot) + (size_t)(uint32_t)(ml0 & 0x7fffffff) * DDIM + colb);
        pf_l2(((ml1 < 0) ? c_buf : c_bot) + (size_t)(uint32_t)(ml1 & 0x7fffffff) * DDIM + colb);
        pf_l2(((mr0 < 0) ? c_buf : c_bot) + (size_t)(uint32_t)(mr0 & 0x7fffffff) * DDIM + colb);
        pf_l2(((mr1 < 0) ? c_buf : c_bot) + (size_t)(uint32_t)(mr1 & 0x7fffffff) * DDIM + colb);
    }

    // ---- pass 1: f_l & f_r together ----
    run_pass<2, 16, 2>(g_Bpack + 65536, g_Bpack + 131072, smem, sbase, tid, wm, wq, lane, acc);
    {
        int ml0 = mapl_s[row0], ml1 = mapl_s[row0 + 8];
        int mr0 = mapr_s[row0], mr1 = mapr_s[row0 + 8];
        const float* cl0 = ((ml0 < 0) ? c_buf : c_bot) + (size_t)(uint32_t)(ml0 & 0x7fffffff) * DDIM;
        const float* cl1 = ((ml1 < 0) ? c_buf : c_bot) + (size_t)(uint32_t)(ml1 & 0x7fffffff) * DDIM;
        const float* cr0 = ((mr0 < 0) ? c_buf : c_bot) + (size_t)(uint32_t)(mr0 & 0x7fffffff) * DDIM;
        const float* cr1 = ((mr1 < 0) ? c_buf : c_bot) + (size_t)(uint32_t)(mr1 & 0x7fffffff) * DDIM;
        #pragma unroll
        for (int ni = 0; ni < 4; ni++) {
            int colg = wq * 32 + ni * 8 + tig * 2;
            float2 bl = *(const float2*)(bias_s + 384 + colg);   // f_l
            float2 br = *(const float2*)(bias_s + 512 + colg);   // f_r
            float2 vl0 = *(const float2*)(cl0 + colg);
            float2 vl1 = *(const float2*)(cl1 + colg);
            float2 vr0 = *(const float2*)(cr0 + colg);
            float2 vr1 = *(const float2*)(cr1 + colg);
            creg[ni][0] = fmaf(sigf(acc[0][ni][0] + bl.x), vl0.x, creg[ni][0]);
            creg[ni][1] = fmaf(sigf(acc[0][ni][1] + bl.y), vl0.y, creg[ni][1]);
            creg[ni][2] = fmaf(sigf(acc[0][ni][2] + bl.x), vl1.x, creg[ni][2]);
            creg[ni][3] = fmaf(sigf(acc[0][ni][3] + bl.y), vl1.y, creg[ni][3]);
            creg[ni][0] = fmaf(sigf(acc[1][ni][0] + br.x), vr0.x, creg[ni][0]);
            creg[ni][1] = fmaf(sigf(acc[1][ni][1] + br.y), vr0.y, creg[ni][1]);
            creg[ni][2] = fmaf(sigf(acc[1][ni][2] + br.x), vr1.x, creg[ni][2]);
            creg[ni][3] = fmaf(sigf(acc[1][ni][3] + br.y), vr1.y, creg[ni][3]);
        }
    }

    // ---- pass 2: o -> finalize h, c ----
    run_pass<1, 8, 4>(g_Bpack + 131072, nullptr, smem, sbase, tid, wm, wq, lane, acc);
    {
        size_t m0 = (size_t)(blk * 32 + row0);
        size_t m1 = m0 + 8;
        #pragma unroll
        for (int ni = 0; ni < 4; ni++) {
            int colg = wq * 32 + ni * 8 + tig * 2;
            float2 bo = *(const float2*)(bias_s + 128 + colg);   // o: cols 128..255
            float2 h0, h1, c0, c1;
            c0.x = creg[ni][0]; h0.x = sigf(acc[0][ni][0] + bo.x) * tanhf_(c0.x);
            c0.y = creg[ni][1]; h0.y = sigf(acc[0][ni][1] + bo.y) * tanhf_(c0.y);
            c1.x = creg[ni][2]; h1.x = sigf(acc[0][ni][2] + bo.x) * tanhf_(c1.x);
            c1.y = creg[ni][3]; h1.y = sigf(acc[0][ni][3] + bo.y) * tanhf_(c1.y);
            *(float2*)(out + m0 * DDIM + colg) = h0;
            *(float2*)(out + m1 * DDIM + colg) = h1;
            *(float2*)(out + (size_t)MROWS * DDIM + m0 * DDIM + colg) = c0;
            *(float2*)(out + (size_t)MROWS * DDIM + m1 * DDIM + colg) = c1;
        }
    }
}

// ---------------- launch ----------------
extern "C" void kernel_launch(void* const* d_in, const int* in_sizes, int n_in,
                              void* d_out, int out_size) {
    const float* h_bot = (const float*)d_in[0];
    const float* c_bot = (const float*)d_in[1];
    const float* h_buf = (const float*)d_in[2];
    const float* c_buf = (const float*)d_in[3];
    const float* W     = (const float*)d_in[4];
    const float* b     = (const float*)d_in[5];
    const int* bf0 = (const int*)d_in[6];
    const int* bt0 = (const int*)d_in[7];
    const int* pf0 = (const int*)d_in[8];
    const int* pt0 = (const int*)d_in[9];
    const int* bf1 = (const int*)d_in[10];
    const int* bt1 = (const int*)d_in[11];
    const int* pf1 = (const int*)d_in[12];
    const int* pt1 = (const int*)d_in[13];
    float* out = (float*)d_out;

    cudaFuncSetAttribute(treelstm_main, cudaFuncAttributeMaxDynamicSharedMemorySize, SMEM_TOTAL);

    prep_all<<<640, 256>>>(W, bf0, bt0, pf0, pt0, bf1, bt1, pf1, pt1);
    treelstm_main<<<MROWS / 32, 256, SMEM_TOTAL>>>(h_bot, c_bot, h_buf, c_buf, b, out);
}